// round 1
// baseline (speedup 1.0000x reference)
#include <cuda_runtime.h>
#include <cuda_bf16.h>
#include <math.h>

#define N_PL 16
#define OBJ  10
#define MOBJ 36

// plin: cw = cumsum of normalized |w|, ww = normalized |w| (17 entries each)
__device__ __forceinline__ float plin_eval(const float* __restrict__ cw,
                                           const float* __restrict__ ww,
                                           float x) {
    float y = 16.0f * x;
    int idx = (int)y;                 // trunc toward zero (x >= 0 in practice)
    float f = y - truncf(y);
    if (idx < 0) idx = 0;             // safety (jnp clamps OOB gather)
    int i0 = idx < N_PL ? idx : N_PL;
    int i1 = (idx + 1) < N_PL ? (idx + 1) : N_PL;
    return cw[i0] + f * ww[i1];
}

__global__ __launch_bounds__(128, 12)
void counter_kernel(const float* __restrict__ boxes,      // [n, 4, 36]
                    const float* __restrict__ attention,  // [n, 36]
                    const float* __restrict__ ws,         // [8, 17]
                    float* __restrict__ out,              // [n, 11]
                    int n) {
    __shared__ float cw[8][N_PL + 1];
    __shared__ float wwv[8][N_PL + 1];
    __shared__ float araw[MOBJ];
    __shared__ float att[OBJ];
    __shared__ float box[4][OBJ];
    __shared__ float dist[OBJ * OBJ];
    __shared__ float scoreA[OBJ * OBJ];
    __shared__ float dedup[OBJ * OBJ];
    __shared__ float simS[OBJ * OBJ];
    __shared__ float rsum[OBJ];
    __shared__ float red[4][3];
    __shared__ float bc[2];   // [total, conf]

    const int row = blockIdx.x;
    if (row >= n) return;
    const int t = threadIdx.x;

    // ---- plin tables: |w| / sum, cumsum (threads 0..7, one ws row each) ----
    if (t < 8) {
        float w[N_PL + 1];
        float s = 0.0f;
        #pragma unroll
        for (int i = 0; i <= N_PL; i++) { w[i] = fabsf(ws[t * (N_PL + 1) + i]); s += w[i]; }
        float inv = 1.0f / s;
        float c = 0.0f;
        #pragma unroll
        for (int i = 0; i <= N_PL; i++) {
            float wn = w[i] * inv;
            wwv[t][i] = wn;
            c += wn;
            cw[t][i] = c;
        }
    }
    // ---- load raw attention (threads 32..67, disjoint from table threads) ----
    if (t >= 32 && t < 32 + MOBJ) {
        araw[t - 32] = attention[(size_t)row * MOBJ + (t - 32)];
    }
    __syncthreads();

    // ---- top-10 by rank count (output is invariant to selection order) ----
    if (t < MOBJ) {
        float v = araw[t];
        int r = 0;
        #pragma unroll
        for (int j = 0; j < MOBJ; j++) {
            float aj = araw[j];
            r += (aj > v) || (aj == v && j < t);
        }
        if (r < OBJ) {
            att[r] = 1.0f / (1.0f + expf(-v));
            const float* bp = boxes + (size_t)row * (4 * MOBJ) + t;
            box[0][r] = bp[0];
            box[1][r] = bp[MOBJ];
            box[2][r] = bp[2 * MOBJ];
            box[3][r] = bp[3 * MOBJ];
        }
    }
    __syncthreads();

    // ---- pairwise: dist = 1-IoU, score, dedup, dist_conf partials ----
    float dconf = 0.0f;
    if (t < OBJ * OBJ) {
        int j = t / OBJ, k = t % OBJ;
        float ax0 = box[0][j], ay0 = box[1][j], ax1 = box[2][j], ay1 = box[3][j];
        float bx0 = box[0][k], by0 = box[1][k], bx1 = box[2][k], by1 = box[3][k];
        float iw = fmaxf(fminf(ax1, bx1) - fmaxf(ax0, bx0), 0.0f);
        float ih = fmaxf(fminf(ay1, by1) - fmaxf(ay0, by0), 0.0f);
        float inter = iw * ih;
        float aa = fmaxf(ax1 - ax0, 0.0f) * fmaxf(ay1 - ay0, 0.0f);
        float ab = fmaxf(bx1 - bx0, 0.0f) * fmaxf(by1 - by0, 0.0f);
        float iou = inter / (aa + ab - inter + 1e-12f);
        float d = 1.0f - iou;
        dist[t] = d;
        float rel = att[j] * att[k];
        scoreA[t] = plin_eval(cw[0], wwv[0], rel) * plin_eval(cw[1], wwv[1], d);
        dedup[t]  = plin_eval(cw[3], wwv[3], rel) * plin_eval(cw[4], wwv[4], d);
        dconf = fabsf(plin_eval(cw[6], wwv[6], d) - 0.5f);
    }
    __syncthreads();

    // ---- sim[j][k] = prod_i plin2(1-|dedup[i][j]-dedup[i][k]|) * plin2(1-|att_j-att_k|) ----
    if (t < OBJ * OBJ) {
        int j = t / OBJ, k = t % OBJ;
        float p = 1.0f;
        #pragma unroll
        for (int i = 0; i < OBJ; i++) {
            float diff = fabsf(dedup[i * OBJ + j] - dedup[i * OBJ + k]);
            p *= plin_eval(cw[2], wwv[2], 1.0f - diff);
        }
        p *= plin_eval(cw[2], wwv[2], 1.0f - fabsf(att[j] - att[k]));
        simS[t] = p;
    }
    __syncthreads();

    // ---- row_sims ----
    if (t < OBJ) {
        float s = 0.0f;
        #pragma unroll
        for (int k = 0; k < OBJ; k++) s += simS[t * OBJ + k];
        rsum[t] = s;
    }
    __syncthreads();

    // ---- partial sums: normalized score + correction + att_conf ----
    float s_total = 0.0f, aconf = 0.0f;
    if (t < OBJ * OBJ) {
        int j = t / OBJ, k = t % OBJ;
        s_total = scoreA[t] / (rsum[j] * rsum[k]);
    }
    if (t < OBJ) {
        float a = att[t];
        s_total += plin_eval(cw[0], wwv[0], a * a) / rsum[t];
        aconf = fabsf(plin_eval(cw[5], wwv[5], a) - 0.5f);
    }

    // ---- block-wide reduction of (s_total, aconf, dconf) ----
    #pragma unroll
    for (int o = 16; o > 0; o >>= 1) {
        s_total += __shfl_down_sync(0xffffffffu, s_total, o);
        aconf   += __shfl_down_sync(0xffffffffu, aconf, o);
        dconf   += __shfl_down_sync(0xffffffffu, dconf, o);
    }
    int w = t >> 5, l = t & 31;
    if (l == 0) { red[w][0] = s_total; red[w][1] = aconf; red[w][2] = dconf; }
    __syncthreads();

    if (t == 0) {
        float S1 = 0.0f, S2 = 0.0f, S3 = 0.0f;
        #pragma unroll
        for (int i = 0; i < 4; i++) { S1 += red[i][0]; S2 += red[i][1]; S3 += red[i][2]; }
        float total = sqrtf(S1 + 1e-20f);
        float conf = plin_eval(cw[7], wwv[7], S2 * 0.1f + S3 * 0.01f);
        bc[0] = total;
        bc[1] = conf;
    }
    __syncthreads();

    // ---- one_hot interpolation * conf, write 11 outputs ----
    if (t < OBJ + 1) {
        float total = bc[0], conf = bc[1];
        float s = fminf(fmaxf(total, 0.0f), (float)OBJ);
        int i = (int)s;
        float f = s - truncf(s);
        int il = i < OBJ ? i : OBJ;
        int ir = (i + 1) < OBJ ? (i + 1) : OBJ;
        float v = (1.0f - f) * (t == il ? 1.0f : 0.0f) + f * (t == ir ? 1.0f : 0.0f);
        out[(size_t)row * (OBJ + 1) + t] = v * conf;
    }
}

extern "C" void kernel_launch(void* const* d_in, const int* in_sizes, int n_in,
                              void* d_out, int out_size) {
    const float* boxes     = (const float*)d_in[0];
    const float* attention = (const float*)d_in[1];
    const float* ws        = (const float*)d_in[2];
    float* out = (float*)d_out;
    int n = in_sizes[1] / MOBJ;
    counter_kernel<<<n, 128>>>(boxes, attention, ws, out, n);
}